// round 1
// baseline (speedup 1.0000x reference)
#include <cuda_runtime.h>

#define BB 4
#define CC 128
#define CO 64
#define NN 4096
#define TM 64

// Scratch (device globals: allocation-free per harness rules)
__device__ float Qd[BB * NN * CO];   // [b][n][o]
__device__ float Kd[BB * CO * NN];   // [b][o][n]
__device__ float Vd[BB * CO * NN];   // [b][o][n]
__device__ float Od[BB * CO * NN];   // [b][o][n] attention output

// ---------------------------------------------------------------------------
// Projection: out = w @ x + bias  (per-pixel 1x1 conv)
// x: [B][C][N], w: [Co][C], out: Kd/Vd layout [B][Co][N] or Qd layout [B][N][Co]
// ---------------------------------------------------------------------------
__global__ void __launch_bounds__(256) proj_kernel(
    const float* __restrict__ x, const float* __restrict__ w,
    const float* __restrict__ bias, float* __restrict__ out, int transposeStore)
{
    extern __shared__ float sm[];
    float* Xs = sm;             // [128][64]
    float* Ws = sm + CC * 64;   // [64][128]

    int b  = blockIdx.y;
    int n0 = blockIdx.x * 64;
    int tid = threadIdx.x;

    const float* xb = x + (size_t)b * CC * NN;
    for (int idx = tid; idx < CC * 64; idx += 256) {
        int c = idx >> 6, j = idx & 63;
        Xs[idx] = xb[c * NN + n0 + j];
    }
    for (int idx = tid; idx < CO * CC; idx += 256) Ws[idx] = w[idx];
    __syncthreads();

    int nx = tid & 63;
    int ty = tid >> 6;   // 0..3
    float acc[16];
#pragma unroll
    for (int i = 0; i < 16; i++) acc[i] = 0.f;

#pragma unroll 4
    for (int c = 0; c < CC; c += 2) {
        float x0 = Xs[c * 64 + nx];
        float x1 = Xs[(c + 1) * 64 + nx];
#pragma unroll
        for (int oi = 0; oi < 16; oi++) {
            int o = oi * 4 + ty;
            float2 w2 = *(const float2*)&Ws[o * CC + c];
            acc[oi] += w2.x * x0 + w2.y * x1;
        }
    }

#pragma unroll
    for (int oi = 0; oi < 16; oi++) {
        int o = oi * 4 + ty;
        float v = acc[oi] + bias[o];
        if (transposeStore)
            out[(size_t)b * NN * CO + (size_t)(n0 + nx) * CO + o] = v;
        else
            out[(size_t)b * CO * NN + (size_t)o * NN + n0 + nx] = v;
    }
}

// ---------------------------------------------------------------------------
// Fused flash attention: Od[b][o][n] = sum_m softmax_m(Q[n]·K[:,m]) * V[o][m]
// Block: 256 threads = 8 warps, 64 rows/block (8 rows per warp), TM=64 m-tile.
// ---------------------------------------------------------------------------
__global__ void __launch_bounds__(256) attn_kernel()
{
    extern __shared__ float sm[];
    float* Ks  = sm;                  // [64][64]   o-major (score operand)
    float* Vst = sm + 64 * 64;        // [64][65]   m-major transposed V
    float* Qs  = Vst + 64 * 65;       // [64 rows][64]
    float* Ps  = Qs + 64 * 64;        // [64 rows][64] softmax probs

    int b  = blockIdx.y;
    int n0 = blockIdx.x * 64;
    int tid  = threadIdx.x;
    int lane = tid & 31;
    int wid  = tid >> 5;
    int r0   = wid * 8;

    const float* Qb = Qd + (size_t)b * NN * CO;
    const float* Kb = Kd + (size_t)b * CO * NN;
    const float* Vb = Vd + (size_t)b * CO * NN;

    for (int idx = tid; idx < 64 * CO; idx += 256)
        Qs[idx] = Qb[(size_t)(n0 + (idx >> 6)) * CO + (idx & 63)];

    float M[8], L[8], acc0[8], acc1[8];
#pragma unroll
    for (int r = 0; r < 8; r++) { M[r] = -1e30f; L[r] = 0.f; acc0[r] = 0.f; acc1[r] = 0.f; }

    int mloc = lane * 2;

    for (int t = 0; t < NN / TM; t++) {
        int m0 = t * TM;
        __syncthreads();
        for (int idx = tid; idx < CO * TM; idx += 256) {
            int c = idx >> 6, m = idx & 63;
            float kval = Kb[(size_t)c * NN + m0 + m];
            float vval = Vb[(size_t)c * NN + m0 + m];
            Ks[c * 64 + m]  = kval;
            Vst[m * 65 + c] = vval;
        }
        __syncthreads();

        // ---- scores: s[m] = sum_c Qs[row][c] * Ks[c][m], 2 m per lane ----
        float s0[8], s1[8];
#pragma unroll
        for (int r = 0; r < 8; r++) { s0[r] = 0.f; s1[r] = 0.f; }

#pragma unroll 8
        for (int c = 0; c < CO; c += 2) {
            float2 ka = *(const float2*)&Ks[c * 64 + mloc];
            float2 kb2 = *(const float2*)&Ks[(c + 1) * 64 + mloc];
#pragma unroll
            for (int r = 0; r < 8; r++) {
                float2 q2 = *(const float2*)&Qs[(r0 + r) * 64 + c];
                s0[r] += q2.x * ka.x + q2.y * kb2.x;
                s1[r] += q2.x * ka.y + q2.y * kb2.y;
            }
        }

        // ---- online softmax update ----
#pragma unroll
        for (int r = 0; r < 8; r++) {
            float mx = fmaxf(s0[r], s1[r]);
#pragma unroll
            for (int off = 16; off > 0; off >>= 1)
                mx = fmaxf(mx, __shfl_xor_sync(0xffffffffu, mx, off));
            float newM = fmaxf(M[r], mx);
            float corr = __expf(M[r] - newM);
            float p0 = __expf(s0[r] - newM);
            float p1 = __expf(s1[r] - newM);
            float ls = p0 + p1;
#pragma unroll
            for (int off = 16; off > 0; off >>= 1)
                ls += __shfl_xor_sync(0xffffffffu, ls, off);
            L[r] = L[r] * corr + ls;
            acc0[r] *= corr;
            acc1[r] *= corr;
            M[r] = newM;
            *(float2*)&Ps[(r0 + r) * 64 + mloc] = make_float2(p0, p1);
        }
        __syncwarp();

        // ---- PV: acc[o] += sum_m Ps[row][m] * V[o][m], o = lane, lane+32 ----
#pragma unroll 4
        for (int m = 0; m < TM; m += 2) {
            float v00 = Vst[m * 65 + lane];
            float v01 = Vst[m * 65 + lane + 32];
            float v10 = Vst[(m + 1) * 65 + lane];
            float v11 = Vst[(m + 1) * 65 + lane + 32];
#pragma unroll
            for (int r = 0; r < 8; r++) {
                float2 p = *(const float2*)&Ps[(r0 + r) * 64 + m];
                acc0[r] += p.x * v00 + p.y * v10;
                acc1[r] += p.x * v01 + p.y * v11;
            }
        }
    }

    // ---- normalize + coalesced store via smem transpose staging ----
    __syncthreads();            // everyone done reading Vst
    float* stg = Vst;           // reuse [64 o][65] region
#pragma unroll
    for (int r = 0; r < 8; r++) {
        float inv = 1.0f / L[r];
        stg[lane * 65 + r0 + r]        = acc0[r] * inv;
        stg[(lane + 32) * 65 + r0 + r] = acc1[r] * inv;
    }
    __syncthreads();
    float* Ob = Od + (size_t)b * CO * NN;
    for (int idx = tid; idx < CO * 64; idx += 256) {
        int o = idx >> 6, rr = idx & 63;
        Ob[(size_t)o * NN + n0 + rr] = stg[o * 65 + rr];
    }
}

// ---------------------------------------------------------------------------
// Epilogue: y = wc @ Od + bc -> BN -> ReLU -> out = img + y
// ---------------------------------------------------------------------------
__global__ void __launch_bounds__(256) out_kernel(
    const float* __restrict__ img, const float* __restrict__ wc,
    const float* __restrict__ bc, const float* __restrict__ gamma,
    const float* __restrict__ beta, const float* __restrict__ mean,
    const float* __restrict__ var, float* __restrict__ out)
{
    extern __shared__ float sm[];
    float* Os = sm;             // [64 o][64 n]
    float* Ws = sm + 64 * 64;   // [128 c][64 o]

    int b  = blockIdx.y;
    int n0 = blockIdx.x * 64;
    int tid = threadIdx.x;

    const float* Ob = Od + (size_t)b * CO * NN;
    for (int idx = tid; idx < CO * 64; idx += 256) {
        int o = idx >> 6, j = idx & 63;
        Os[idx] = Ob[(size_t)o * NN + n0 + j];
    }
    for (int idx = tid; idx < CC * CO; idx += 256) Ws[idx] = wc[idx];
    __syncthreads();

    int nx = (tid & 15) * 4;    // 4 consecutive n
    int cg = tid >> 4;          // 16 groups of 8 channels
    float acc[8][4];
#pragma unroll
    for (int i = 0; i < 8; i++)
#pragma unroll
        for (int j = 0; j < 4; j++) acc[i][j] = 0.f;

#pragma unroll 4
    for (int o = 0; o < CO; o += 2) {
        float4 a0 = *(const float4*)&Os[o * 64 + nx];
        float4 a1 = *(const float4*)&Os[(o + 1) * 64 + nx];
#pragma unroll
        for (int ci = 0; ci < 8; ci++) {
            int c = cg * 8 + ci;
            float2 w2 = *(const float2*)&Ws[c * CO + o];
            acc[ci][0] += w2.x * a0.x + w2.y * a1.x;
            acc[ci][1] += w2.x * a0.y + w2.y * a1.y;
            acc[ci][2] += w2.x * a0.z + w2.y * a1.z;
            acc[ci][3] += w2.x * a0.w + w2.y * a1.w;
        }
    }

#pragma unroll
    for (int ci = 0; ci < 8; ci++) {
        int c = cg * 8 + ci;
        float inv   = gamma[c] * rsqrtf(var[c] + 1e-5f);
        float shift = beta[c] - mean[c] * inv;
        float bias  = bc[c];
        size_t base = (size_t)b * CC * NN + (size_t)c * NN + n0 + nx;
        float4 iv = *(const float4*)&img[base];
        float4 r;
        float y;
        y = (acc[ci][0] + bias) * inv + shift; r.x = iv.x + fmaxf(y, 0.f);
        y = (acc[ci][1] + bias) * inv + shift; r.y = iv.y + fmaxf(y, 0.f);
        y = (acc[ci][2] + bias) * inv + shift; r.z = iv.z + fmaxf(y, 0.f);
        y = (acc[ci][3] + bias) * inv + shift; r.w = iv.w + fmaxf(y, 0.f);
        *(float4*)&out[base] = r;
    }
}

// ---------------------------------------------------------------------------
extern "C" void kernel_launch(void* const* d_in, const int* in_sizes, int n_in,
                              void* d_out, int out_size)
{
    const float* range_x = (const float*)d_in[0];
    const float* img     = (const float*)d_in[1];
    const float* wq      = (const float*)d_in[2];
    const float* bq      = (const float*)d_in[3];
    const float* wk      = (const float*)d_in[4];
    const float* bk      = (const float*)d_in[5];
    const float* wv      = (const float*)d_in[6];
    const float* bv      = (const float*)d_in[7];
    const float* wc      = (const float*)d_in[8];
    const float* bc      = (const float*)d_in[9];
    const float* g       = (const float*)d_in[10];
    const float* be      = (const float*)d_in[11];
    const float* mn      = (const float*)d_in[12];
    const float* vr      = (const float*)d_in[13];
    float* out = (float*)d_out;

    float *Qp, *Kp, *Vp;
    cudaGetSymbolAddress((void**)&Qp, Qd);
    cudaGetSymbolAddress((void**)&Kp, Kd);
    cudaGetSymbolAddress((void**)&Vp, Vd);

    int smProj = (CC * 64 + CO * CC) * sizeof(float);           // 64 KB
    int smAttn = (64 * 64 + 64 * 65 + 64 * 64 + 64 * 64) * sizeof(float);  // ~64.3 KB
    int smOut  = (64 * 64 + CC * CO) * sizeof(float);           // 48 KB

    cudaFuncSetAttribute(proj_kernel, cudaFuncAttributeMaxDynamicSharedMemorySize, smProj);
    cudaFuncSetAttribute(attn_kernel, cudaFuncAttributeMaxDynamicSharedMemorySize, smAttn);
    cudaFuncSetAttribute(out_kernel,  cudaFuncAttributeMaxDynamicSharedMemorySize, smOut);

    dim3 grid(NN / 64, BB);
    proj_kernel<<<grid, 256, smProj>>>(range_x, wq, bq, Qp, 1);  // Q: [b][n][o]
    proj_kernel<<<grid, 256, smProj>>>(img,     wk, bk, Kp, 0);  // K: [b][o][n]
    proj_kernel<<<grid, 256, smProj>>>(img,     wv, bv, Vp, 0);  // V: [b][o][n]
    attn_kernel<<<grid, 256, smAttn>>>();
    out_kernel<<<grid, 256, smOut>>>(img, wc, bc, g, be, mn, vr, out);
}

// round 3
// speedup vs baseline: 2.9067x; 2.9067x over previous
#include <cuda_runtime.h>
#include <cuda_bf16.h>
#include <cstdint>

#define BB 4
#define CC 128
#define CO 64
#define NN 4096
#define TQ 128
#define TMT 128
#define NSTEP (NN / TMT)

// ---------------- scratch (device globals) ----------------------------------
__device__ __align__(16) __nv_bfloat16 QhG[BB * NN * CO];
__device__ __align__(16) __nv_bfloat16 QlG[BB * NN * CO];
__device__ __align__(16) __nv_bfloat16 KhG[BB * NN * CO];
__device__ __align__(16) __nv_bfloat16 KlG[BB * NN * CO];
__device__ __align__(16) __nv_bfloat16 VhG[BB * NN * CO];   // token-major [b][m][o]
__device__ __align__(16) __nv_bfloat16 VlG[BB * NN * CO];
__device__ float OdG[BB * CO * NN];

// ---------------- helpers ----------------------------------------------------
__device__ __forceinline__ uint32_t smem_u32(const void* p) {
    uint32_t a;
    asm("{ .reg .u64 t; cvta.to.shared.u64 t, %1; cvt.u32.u64 %0, t; }"
        : "=r"(a) : "l"(p));
    return a;
}
__device__ __forceinline__ float ex2f(float x) {
    float y; asm("ex2.approx.f32 %0, %1;" : "=f"(y) : "f"(x)); return y;
}
#define SWZ128(off) ((off) ^ (((off) >> 3) & 0x70))

#define LDSM_X4(r0,r1,r2,r3,addr) \
    asm volatile("ldmatrix.sync.aligned.m8n8.x4.shared.b16 {%0,%1,%2,%3}, [%4];" \
        : "=r"(r0),"=r"(r1),"=r"(r2),"=r"(r3) : "r"(addr))
#define LDSM_X4T(r0,r1,r2,r3,addr) \
    asm volatile("ldmatrix.sync.aligned.m8n8.x4.trans.shared.b16 {%0,%1,%2,%3}, [%4];" \
        : "=r"(r0),"=r"(r1),"=r"(r2),"=r"(r3) : "r"(addr))

#define MMA16816(c0,c1,c2,c3,a0,a1,a2,a3,b0,b1) \
    asm volatile("mma.sync.aligned.m16n8k16.row.col.f32.bf16.bf16.f32 " \
        "{%0,%1,%2,%3}, {%4,%5,%6,%7}, {%8,%9}, {%0,%1,%2,%3};" \
        : "+f"(c0),"+f"(c1),"+f"(c2),"+f"(c3) \
        : "r"(a0),"r"(a1),"r"(a2),"r"(a3),"r"(b0),"r"(b1))

__device__ __forceinline__ void cpa16(uint32_t dst, const void* src) {
    asm volatile("cp.async.cg.shared.global [%0], [%1], 16;" :: "r"(dst), "l"(src));
}
#define CP_COMMIT() asm volatile("cp.async.commit_group;" ::: "memory")
#define CP_WAIT(n)  asm volatile("cp.async.wait_group %0;" :: "n"(n) : "memory")

__device__ __forceinline__ uint32_t pack_bf16(float lo, float hi) {
    uint32_t r;
    asm("cvt.rn.bf16x2.f32 %0, %1, %2;" : "=r"(r) : "f"(hi), "f"(lo));
    return r;
}

// one 128x64-bf16 array (16KB) -> smem with SW128 swizzle, 4 cp.async/thread
__device__ __forceinline__ void load_arr(uint32_t dst, const __nv_bfloat16* src, int tid) {
#pragma unroll
    for (int it = 0; it < 4; it++) {
        int i = tid + it * 256;
        int row = i >> 3, ch = i & 7;
        cpa16(dst + SWZ128((uint32_t)(row * 128 + ch * 16)),
              src + (size_t)row * CO + ch * 8);
    }
}

// ---------------------------------------------------------------------------
// Projection + split-bf16 store.  x:[B][C][N], w:[Co][C]. out [b][n][o].
// ---------------------------------------------------------------------------
__global__ void __launch_bounds__(256) proj_split_kernel(
    const float* __restrict__ x, const float* __restrict__ w,
    const float* __restrict__ bias, float scale,
    __nv_bfloat16* __restrict__ hi, __nv_bfloat16* __restrict__ lo)
{
    extern __shared__ float sm[];
    float* Xs = sm;
    float* Ws = sm + CC * 64;

    int b  = blockIdx.y;
    int n0 = blockIdx.x * 64;
    int tid = threadIdx.x;

    const float* xb = x + (size_t)b * CC * NN;
    for (int idx = tid; idx < CC * 64; idx += 256) {
        int c = idx >> 6, j = idx & 63;
        Xs[idx] = xb[c * NN + n0 + j];
    }
    for (int idx = tid; idx < CO * CC; idx += 256) Ws[idx] = w[idx];
    __syncthreads();

    int nx = tid & 63;
    int ty = tid >> 6;
    float acc[16];
#pragma unroll
    for (int i = 0; i < 16; i++) acc[i] = 0.f;

#pragma unroll 4
    for (int c = 0; c < CC; c += 2) {
        float x0 = Xs[c * 64 + nx];
        float x1 = Xs[(c + 1) * 64 + nx];
#pragma unroll
        for (int oi = 0; oi < 16; oi++) {
            int o = oi * 4 + ty;
            float2 w2 = *(const float2*)&Ws[o * CC + c];
            acc[oi] += w2.x * x0 + w2.y * x1;
        }
    }

#pragma unroll
    for (int oi = 0; oi < 16; oi++) {
        int o = oi * 4 + ty;
        float v = (acc[oi] + bias[o]) * scale;
        __nv_bfloat16 h = __float2bfloat16(v);
        __nv_bfloat16 l = __float2bfloat16(v - __bfloat162float(h));
        size_t addr = ((size_t)b * NN + n0 + nx) * CO + o;
        hi[addr] = h;
        lo[addr] = l;
    }
}

// ---------------------------------------------------------------------------
// FA2-style attention with mma.sync bf16 splits.
// smem: 2 stages x 64KB: [Kh 16K][Kl 16K][Vh 16K][Vl 16K]
// ---------------------------------------------------------------------------
#define STG_BYTES 65536
#define SMEM_ATTN (2 * STG_BYTES)

__global__ void __launch_bounds__(256, 1) attn_mma_kernel(float* __restrict__ Od)
{
    extern __shared__ char smem[];
    const uint32_t sb = smem_u32(smem);

    int tid  = threadIdx.x;
    int lane = tid & 31;
    int wid  = tid >> 5;
    int b    = blockIdx.y;
    int n0   = blockIdx.x * TQ;
    int r0   = wid * 16;

    const __nv_bfloat16* gQh = QhG + ((size_t)b * NN + n0) * CO;
    const __nv_bfloat16* gQl = QlG + ((size_t)b * NN + n0) * CO;
    size_t kb = (size_t)b * NN * CO;

    // ---- stage Q hi/lo into stage0 area, load A-fragments to registers ----
    load_arr(sb,         gQh, tid);
    load_arr(sb + 16384, gQl, tid);
    CP_COMMIT();
    CP_WAIT(0);
    __syncthreads();

    uint32_t QH[4][4], QL[4][4];
    {
        int rq = r0 + (lane & 7) + ((lane >> 3) & 1) * 8;
        uint32_t cq = ((lane >> 4) & 1) * 16;
#pragma unroll
        for (int ks = 0; ks < 4; ks++) {
            uint32_t off = SWZ128((uint32_t)(rq * 128 + ks * 32 + cq));
            LDSM_X4(QH[ks][0], QH[ks][1], QH[ks][2], QH[ks][3], sb + off);
            LDSM_X4(QL[ks][0], QL[ks][1], QL[ks][2], QL[ks][3], sb + 16384 + off);
        }
    }
    __syncthreads();

    // ---- prologue: issue tile 0 into stage 0 ----
    load_arr(sb + 0,     KhG + kb, tid);
    load_arr(sb + 16384, KlG + kb, tid);
    load_arr(sb + 32768, VhG + kb, tid);
    load_arr(sb + 49152, VlG + kb, tid);
    CP_COMMIT();

    float Oa[8][4];
#pragma unroll
    for (int i = 0; i < 8; i++)
#pragma unroll
        for (int j = 0; j < 4; j++) Oa[i][j] = 0.f;
    float Lg = 0.f, Lg8 = 0.f;

    for (int t = 0; t < NSTEP; t++) {
        if (t + 1 < NSTEP) {
            uint32_t db = sb + ((t + 1) & 1) * STG_BYTES;
            size_t gb = kb + (size_t)(t + 1) * TMT * CO;
            load_arr(db + 0,     KhG + gb, tid);
            load_arr(db + 16384, KlG + gb, tid);
            load_arr(db + 32768, VhG + gb, tid);
            load_arr(db + 49152, VlG + gb, tid);
            CP_COMMIT();
            CP_WAIT(1);
        } else {
            CP_WAIT(0);
        }
        __syncthreads();

        const uint32_t kh_b = sb + (t & 1) * STG_BYTES;
        const uint32_t kl_b = kh_b + 16384;
        const uint32_t vh_b = kh_b + 32768;
        const uint32_t vl_b = kh_b + 49152;

        uint32_t PH[16][2], PL[16][2];
        {
            int rowk = (lane & 7);
            uint32_t cbk = ((uint32_t)(lane >> 3)) * 16;
#pragma unroll
            for (int mb = 0; mb < 16; mb++) {
                float c0 = 0.f, c1 = 0.f, c2 = 0.f, c3 = 0.f;
#pragma unroll
                for (int kc = 0; kc < 2; kc++) {
                    uint32_t off = SWZ128((uint32_t)((mb * 8 + rowk) * 128 + kc * 64) + cbk);
                    uint32_t k0, k1, k2, k3;
                    LDSM_X4(k0, k1, k2, k3, kh_b + off);
                    MMA16816(c0,c1,c2,c3, QH[2*kc][0],QH[2*kc][1],QH[2*kc][2],QH[2*kc][3], k0,k1);
                    MMA16816(c0,c1,c2,c3, QH[2*kc+1][0],QH[2*kc+1][1],QH[2*kc+1][2],QH[2*kc+1][3], k2,k3);
                    MMA16816(c0,c1,c2,c3, QL[2*kc][0],QL[2*kc][1],QL[2*kc][2],QL[2*kc][3], k0,k1);
                    MMA16816(c0,c1,c2,c3, QL[2*kc+1][0],QL[2*kc+1][1],QL[2*kc+1][2],QL[2*kc+1][3], k2,k3);
                    LDSM_X4(k0, k1, k2, k3, kl_b + off);
                    MMA16816(c0,c1,c2,c3, QH[2*kc][0],QH[2*kc][1],QH[2*kc][2],QH[2*kc][3], k0,k1);
                    MMA16816(c0,c1,c2,c3, QH[2*kc+1][0],QH[2*kc+1][1],QH[2*kc+1][2],QH[2*kc+1][3], k2,k3);
                }
                // unnormalized softmax (Q was pre-scaled by log2 e)
                float p0 = ex2f(c0), p1 = ex2f(c1), p2 = ex2f(c2), p3 = ex2f(c3);
                Lg  += p0 + p1;
                Lg8 += p2 + p3;
                uint32_t h01 = pack_bf16(p0, p1);
                uint32_t h23 = pack_bf16(p2, p3);
                float l0 = p0 - __uint_as_float(h01 << 16);
                float l1 = p1 - __uint_as_float(h01 & 0xFFFF0000u);
                float l2 = p2 - __uint_as_float(h23 << 16);
                float l3 = p3 - __uint_as_float(h23 & 0xFFFF0000u);
                PH[mb][0] = h01; PH[mb][1] = h23;
                PL[mb][0] = pack_bf16(l0, l1); PL[mb][1] = pack_bf16(l2, l3);
            }
        }

        // ---- PV ----
        {
            int rv = (lane & 7) + ((lane >> 3) & 1) * 8;
            uint32_t cbv = ((uint32_t)((lane >> 4) & 1)) * 16;
#pragma unroll
            for (int km = 0; km < 8; km++) {
                uint32_t a0 = PH[2*km][0], a1 = PH[2*km][1];
                uint32_t a2 = PH[2*km+1][0], a3 = PH[2*km+1][1];
                uint32_t e0 = PL[2*km][0], e1 = PL[2*km][1];
                uint32_t e2 = PL[2*km+1][0], e3 = PL[2*km+1][1];
#pragma unroll
                for (int oc = 0; oc < 4; oc++) {
                    uint32_t off = SWZ128((uint32_t)((km * 16 + rv) * 128 + oc * 32) + cbv);
                    uint32_t v0, v1, v2, v3;
                    LDSM_X4T(v0, v1, v2, v3, vh_b + off);
                    MMA16816(Oa[2*oc][0],Oa[2*oc][1],Oa[2*oc][2],Oa[2*oc][3], a0,a1,a2,a3, v0,v1);
                    MMA16816(Oa[2*oc+1][0],Oa[2*oc+1][1],Oa[2*oc+1][2],Oa[2*oc+1][3], a0,a1,a2,a3, v2,v3);
                    MMA16816(Oa[2*oc][0],Oa[2*oc][1],Oa[2*oc][2],Oa[2*oc][3], e0,e1,e2,e3, v0,v1);
                    MMA16816(Oa[2*oc+1][0],Oa[2*oc+1][1],Oa[2*oc+1][2],Oa[2*oc+1][3], e0,e1,e2,e3, v2,v3);
                    LDSM_X4T(v0, v1, v2, v3, vl_b + off);
                    MMA16816(Oa[2*oc][0],Oa[2*oc][1],Oa[2*oc][2],Oa[2*oc][3], a0,a1,a2,a3, v0,v1);
                    MMA16816(Oa[2*oc+1][0],Oa[2*oc+1][1],Oa[2*oc+1][2],Oa[2*oc+1][3], a0,a1,a2,a3, v2,v3);
                }
            }
        }
        __syncthreads();
    }

    // ---- reduce row sums over quad, normalize, stage, store ----
    Lg  += __shfl_xor_sync(0xffffffffu, Lg, 1);
    Lg  += __shfl_xor_sync(0xffffffffu, Lg, 2);
    Lg8 += __shfl_xor_sync(0xffffffffu, Lg8, 1);
    Lg8 += __shfl_xor_sync(0xffffffffu, Lg8, 2);
    float invg = 1.f / Lg, invg8 = 1.f / Lg8;

    float* stg = (float*)smem;      // 64 o x 128 r fp32 = 32KB (stage0 area)
    int g = lane >> 2, u = lane & 3;
    int rA = r0 + g, rB = r0 + 8 + g;
#pragma unroll
    for (int ob = 0; ob < 8; ob++) {
        int o0 = ob * 8 + 2 * u;
        stg[o0 * 128 + rA]       = Oa[ob][0] * invg;
        stg[(o0 + 1) * 128 + rA] = Oa[ob][1] * invg;
        stg[o0 * 128 + rB]       = Oa[ob][2] * invg8;
        stg[(o0 + 1) * 128 + rB] = Oa[ob][3] * invg8;
    }
    __syncthreads();
    for (int idx = tid; idx < CO * TQ; idx += 256) {
        int o = idx >> 7, r = idx & 127;
        Od[((size_t)b * CO + o) * NN + n0 + r] = stg[idx];
    }
}

// ---------------------------------------------------------------------------
// Epilogue: y = wc @ Od + bc -> BN -> ReLU -> out = img + y
// ---------------------------------------------------------------------------
__global__ void __launch_bounds__(256) out_kernel(
    const float* __restrict__ img, const float* __restrict__ wc,
    const float* __restrict__ bc, const float* __restrict__ gamma,
    const float* __restrict__ beta, const float* __restrict__ mean,
    const float* __restrict__ var, float* __restrict__ out)
{
    extern __shared__ float sm[];
    float* Os = sm;
    float* Ws = sm + 64 * 64;

    int b  = blockIdx.y;
    int n0 = blockIdx.x * 64;
    int tid = threadIdx.x;

    const float* Ob = OdG + (size_t)b * CO * NN;
    for (int idx = tid; idx < CO * 64; idx += 256) {
        int o = idx >> 6, j = idx & 63;
        Os[idx] = Ob[(size_t)o * NN + n0 + j];
    }
    for (int idx = tid; idx < CC * CO; idx += 256) Ws[idx] = wc[idx];
    __syncthreads();

    int nx = (tid & 15) * 4;
    int cg = tid >> 4;
    float acc[8][4];
#pragma unroll
    for (int i = 0; i < 8; i++)
#pragma unroll
        for (int j = 0; j < 4; j++) acc[i][j] = 0.f;

#pragma unroll 4
    for (int o = 0; o < CO; o += 2) {
        float4 a0 = *(const float4*)&Os[o * 64 + nx];
        float4 a1 = *(const float4*)&Os[(o + 1) * 64 + nx];
#pragma unroll
        for (int ci = 0; ci < 8; ci++) {
            int c = cg * 8 + ci;
            float2 w2 = *(const float2*)&Ws[c * CO + o];
            acc[ci][0] += w2.x * a0.x + w2.y * a1.x;
            acc[ci][1] += w2.x * a0.y + w2.y * a1.y;
            acc[ci][2] += w2.x * a0.z + w2.y * a1.z;
            acc[ci][3] += w2.x * a0.w + w2.y * a1.w;
        }
    }

#pragma unroll
    for (int ci = 0; ci < 8; ci++) {
        int c = cg * 8 + ci;
        float inv   = gamma[c] * rsqrtf(var[c] + 1e-5f);
        float shift = beta[c] - mean[c] * inv;
        float bias  = bc[c];
        size_t base = (size_t)b * CC * NN + (size_t)c * NN + n0 + nx;
        float4 iv = *(const float4*)&img[base];
        float4 r;
        float y;
        y = (acc[ci][0] + bias) * inv + shift; r.x = iv.x + fmaxf(y, 0.f);
        y = (acc[ci][1] + bias) * inv + shift; r.y = iv.y + fmaxf(y, 0.f);
        y = (acc[ci][2] + bias) * inv + shift; r.z = iv.z + fmaxf(y, 0.f);
        y = (acc[ci][3] + bias) * inv + shift; r.w = iv.w + fmaxf(y, 0.f);
        *(float4*)&out[base] = r;
    }
}

// ---------------------------------------------------------------------------
extern "C" void kernel_launch(void* const* d_in, const int* in_sizes, int n_in,
                              void* d_out, int out_size)
{
    const float* range_x = (const float*)d_in[0];
    const float* img     = (const float*)d_in[1];
    const float* wq      = (const float*)d_in[2];
    const float* bq      = (const float*)d_in[3];
    const float* wk      = (const float*)d_in[4];
    const float* bk      = (const float*)d_in[5];
    const float* wv      = (const float*)d_in[6];
    const float* bv      = (const float*)d_in[7];
    const float* wc      = (const float*)d_in[8];
    const float* bc      = (const float*)d_in[9];
    const float* g       = (const float*)d_in[10];
    const float* be      = (const float*)d_in[11];
    const float* mn      = (const float*)d_in[12];
    const float* vr      = (const float*)d_in[13];
    float* out = (float*)d_out;

    __nv_bfloat16 *qh, *ql, *kh, *kl, *vh, *vl;
    float* od;
    cudaGetSymbolAddress((void**)&qh, QhG);
    cudaGetSymbolAddress((void**)&ql, QlG);
    cudaGetSymbolAddress((void**)&kh, KhG);
    cudaGetSymbolAddress((void**)&kl, KlG);
    cudaGetSymbolAddress((void**)&vh, VhG);
    cudaGetSymbolAddress((void**)&vl, VlG);
    cudaGetSymbolAddress((void**)&od, OdG);

    int smProj = (CC * 64 + CO * CC) * sizeof(float);
    int smOut  = (64 * 64 + CC * CO) * sizeof(float);

    cudaFuncSetAttribute(proj_split_kernel, cudaFuncAttributeMaxDynamicSharedMemorySize, smProj);
    cudaFuncSetAttribute(attn_mma_kernel, cudaFuncAttributeMaxDynamicSharedMemorySize, SMEM_ATTN);
    cudaFuncSetAttribute(out_kernel, cudaFuncAttributeMaxDynamicSharedMemorySize, smOut);

    const float LOG2E = 1.4426950408889634f;
    dim3 gp(NN / 64, BB);
    proj_split_kernel<<<gp, 256, smProj>>>(range_x, wq, bq, LOG2E, qh, ql); // Q (pre-scaled)
    proj_split_kernel<<<gp, 256, smProj>>>(img,     wk, bk, 1.0f,  kh, kl); // K
    proj_split_kernel<<<gp, 256, smProj>>>(img,     wv, bv, 1.0f,  vh, vl); // V

    dim3 ga(NN / TQ, BB);
    attn_mma_kernel<<<ga, 256, SMEM_ATTN>>>(od);

    out_kernel<<<gp, 256, smOut>>>(img, wc, bc, g, be, mn, vr, out);
}

// round 4
// speedup vs baseline: 3.9841x; 1.3707x over previous
#include <cuda_runtime.h>
#include <cuda_bf16.h>
#include <cstdint>

#define BB 4
#define CC 128
#define CO 64
#define NN 4096
#define TQ 64
#define TMT 64
#define NSTEP (NN / TMT)

// ---------------- scratch (device globals) ----------------------------------
__device__ __align__(16) __nv_bfloat16 QhG[BB * NN * CO];
__device__ __align__(16) __nv_bfloat16 QlG[BB * NN * CO];
__device__ __align__(16) __nv_bfloat16 KhG[BB * NN * CO];
__device__ __align__(16) __nv_bfloat16 KlG[BB * NN * CO];
__device__ __align__(16) __nv_bfloat16 VhG[BB * NN * CO];   // token-major [b][m][o]
__device__ __align__(16) __nv_bfloat16 VlG[BB * NN * CO];
__device__ float OdG[BB * CO * NN];

// ---------------- helpers ----------------------------------------------------
__device__ __forceinline__ uint32_t smem_u32(const void* p) {
    uint32_t a;
    asm("{ .reg .u64 t; cvta.to.shared.u64 t, %1; cvt.u32.u64 %0, t; }"
        : "=r"(a) : "l"(p));
    return a;
}
__device__ __forceinline__ float ex2f(float x) {
    float y; asm("ex2.approx.f32 %0, %1;" : "=f"(y) : "f"(x)); return y;
}
#define SWZ128(off) ((off) ^ (((off) >> 3) & 0x70))

#define LDSM_X4(r0,r1,r2,r3,addr) \
    asm volatile("ldmatrix.sync.aligned.m8n8.x4.shared.b16 {%0,%1,%2,%3}, [%4];" \
        : "=r"(r0),"=r"(r1),"=r"(r2),"=r"(r3) : "r"(addr))
#define LDSM_X4T(r0,r1,r2,r3,addr) \
    asm volatile("ldmatrix.sync.aligned.m8n8.x4.trans.shared.b16 {%0,%1,%2,%3}, [%4];" \
        : "=r"(r0),"=r"(r1),"=r"(r2),"=r"(r3) : "r"(addr))

#define MMA16816(c0,c1,c2,c3,a0,a1,a2,a3,b0,b1) \
    asm volatile("mma.sync.aligned.m16n8k16.row.col.f32.bf16.bf16.f32 " \
        "{%0,%1,%2,%3}, {%4,%5,%6,%7}, {%8,%9}, {%0,%1,%2,%3};" \
        : "+f"(c0),"+f"(c1),"+f"(c2),"+f"(c3) \
        : "r"(a0),"r"(a1),"r"(a2),"r"(a3),"r"(b0),"r"(b1))

__device__ __forceinline__ void cpa16(uint32_t dst, const void* src) {
    asm volatile("cp.async.cg.shared.global [%0], [%1], 16;" :: "r"(dst), "l"(src));
}
#define CP_COMMIT() asm volatile("cp.async.commit_group;" ::: "memory")
#define CP_WAIT(n)  asm volatile("cp.async.wait_group %0;" :: "n"(n) : "memory")

__device__ __forceinline__ uint32_t pack_bf16(float lo, float hi) {
    uint32_t r;
    asm("cvt.rn.bf16x2.f32 %0, %1, %2;" : "=r"(r) : "f"(hi), "f"(lo));
    return r;
}

// 64 rows x 64 bf16 (8KB) -> smem SW128, 128 threads, 4 cp.async each
__device__ __forceinline__ void load_arr64(uint32_t dst, const __nv_bfloat16* src, int tid) {
#pragma unroll
    for (int it = 0; it < 4; it++) {
        int i = tid + it * 128;
        int row = i >> 3, ch = i & 7;
        cpa16(dst + SWZ128((uint32_t)(row * 128 + ch * 16)),
              src + (size_t)row * CO + ch * 8);
    }
}

// ---------------------------------------------------------------------------
// Projection(s) + split-bf16 store.  x:[B][C][N]; per set: w:[Co][C], bias.
// out [b][n][o] bf16 hi/lo.  nsets=1 (Q) or 2 (K then V) sharing the x tile.
// smem floats: Xs[128c][64n] | Ws[64o][128c] | stgH 2048 | stgL 2048 = 80KB
// ---------------------------------------------------------------------------
__global__ void __launch_bounds__(256) proj2_kernel(
    const float* __restrict__ x,
    const float* __restrict__ w0, const float* __restrict__ b0, float scale0,
    __nv_bfloat16* __restrict__ hi0, __nv_bfloat16* __restrict__ lo0,
    const float* __restrict__ w1, const float* __restrict__ b1, float scale1,
    __nv_bfloat16* __restrict__ hi1, __nv_bfloat16* __restrict__ lo1,
    int nsets)
{
    extern __shared__ float sm[];
    float* Xs  = sm;                    // 8192
    float* Ws  = sm + 8192;             // 8192
    float* stgH = sm + 16384;           // 2048 (8KB as bf16 pairs)
    float* stgL = sm + 18432;           // 2048

    int b  = blockIdx.y;
    int n0 = blockIdx.x * 64;
    int tid = threadIdx.x;

    // load x tile [128c][64n] (float4)
    const float* xb = x + (size_t)b * CC * NN + n0;
    for (int i = tid; i < 2048; i += 256) {
        int c = i >> 4, j4 = (i & 15) * 4;
        *(float4*)&Xs[c * 64 + j4] = *(const float4*)&xb[(size_t)c * NN + j4];
    }

    int nx = (tid & 15) * 4;
    int og = tid >> 4;               // 0..15 -> o = og*4 + 0..3

    for (int s = 0; s < nsets; s++) {
        const float* w   = s ? w1 : w0;
        const float* bia = s ? b1 : b0;
        float scale      = s ? scale1 : scale0;
        __nv_bfloat16* hi = s ? hi1 : hi0;
        __nv_bfloat16* lo = s ? lo1 : lo0;

        __syncthreads();             // Ws free (prev set done / first pass after x)
        for (int i = tid; i < 2048; i += 256)
            *(float4*)&Ws[i * 4] = *(const float4*)&w[i * 4];
        __syncthreads();

        float acc[4][4];
#pragma unroll
        for (int i = 0; i < 4; i++)
#pragma unroll
            for (int j = 0; j < 4; j++) acc[i][j] = 0.f;

#pragma unroll 4
        for (int c = 0; c < CC; c += 2) {
            float4 xa = *(const float4*)&Xs[c * 64 + nx];
            float4 xb2 = *(const float4*)&Xs[(c + 1) * 64 + nx];
#pragma unroll
            for (int oi = 0; oi < 4; oi++) {
                float2 w2 = *(const float2*)&Ws[(og * 4 + oi) * CC + c];
                acc[oi][0] += w2.x * xa.x + w2.y * xb2.x;
                acc[oi][1] += w2.x * xa.y + w2.y * xb2.y;
                acc[oi][2] += w2.x * xa.z + w2.y * xb2.z;
                acc[oi][3] += w2.x * xa.w + w2.y * xb2.w;
            }
        }

        float bb[4];
#pragma unroll
        for (int oi = 0; oi < 4; oi++) bb[oi] = bia[og * 4 + oi];

        // stage: [n 64][o 64] bf16, o-quad packed as 2x uint32 (8B)
#pragma unroll
        for (int j = 0; j < 4; j++) {
            float v0 = (acc[0][j] + bb[0]) * scale;
            float v1 = (acc[1][j] + bb[1]) * scale;
            float v2 = (acc[2][j] + bb[2]) * scale;
            float v3 = (acc[3][j] + bb[3]) * scale;
            uint32_t h01 = pack_bf16(v0, v1), h23 = pack_bf16(v2, v3);
            float l0 = v0 - __uint_as_float(h01 << 16);
            float l1 = v1 - __uint_as_float(h01 & 0xFFFF0000u);
            float l2 = v2 - __uint_as_float(h23 << 16);
            float l3 = v3 - __uint_as_float(h23 & 0xFFFF0000u);
            int fo = (nx + j) * 32 + og * 2;      // float-offset: n*128B + og*8B
            stgH[fo] = __uint_as_float(h01); stgH[fo + 1] = __uint_as_float(h23);
            uint32_t q01 = pack_bf16(l0, l1), q23 = pack_bf16(l2, l3);
            stgL[fo] = __uint_as_float(q01); stgL[fo + 1] = __uint_as_float(q23);
        }
        __syncthreads();

        // contiguous 8KB block per array
        {
            uint4* dH = (uint4*)(hi + ((size_t)b * NN + n0) * CO);
            uint4* dL = (uint4*)(lo + ((size_t)b * NN + n0) * CO);
            for (int i = tid; i < 512; i += 256) {
                dH[i] = ((uint4*)stgH)[i];
                dL[i] = ((uint4*)stgL)[i];
            }
        }
    }
}

// ---------------------------------------------------------------------------
// FA2-style attention, interleaved softmax/PV.  TQ=64 rows, 4 warps, TMT=64.
// stage (32KB): Kh 8K | Kl 8K | Vh 8K | Vl 8K ; double buffered = 64KB
// ---------------------------------------------------------------------------
#define STG_BYTES 32768
#define SMEM_ATTN (2 * STG_BYTES)

__global__ void __launch_bounds__(128, 2) attn_mma_kernel(float* __restrict__ Od)
{
    extern __shared__ char smem[];
    const uint32_t sb = smem_u32(smem);

    int tid  = threadIdx.x;
    int lane = tid & 31;
    int wid  = tid >> 5;
    int b    = blockIdx.y;
    int n0   = blockIdx.x * TQ;
    int r0   = wid * 16;

    size_t kb = (size_t)b * NN * CO;

    // ---- stage Q hi/lo, load A-fragments ----
    load_arr64(sb,        QhG + ((size_t)b * NN + n0) * CO, tid);
    load_arr64(sb + 8192, QlG + ((size_t)b * NN + n0) * CO, tid);
    CP_COMMIT();
    CP_WAIT(0);
    __syncthreads();

    uint32_t QH[4][4], QL[4][4];
    {
        int rq = r0 + (lane & 7) + ((lane >> 3) & 1) * 8;
        uint32_t cq = ((lane >> 4) & 1) * 16;
#pragma unroll
        for (int ks = 0; ks < 4; ks++) {
            uint32_t off = SWZ128((uint32_t)(rq * 128 + ks * 32 + cq));
            LDSM_X4(QH[ks][0], QH[ks][1], QH[ks][2], QH[ks][3], sb + off);
            LDSM_X4(QL[ks][0], QL[ks][1], QL[ks][2], QL[ks][3], sb + 8192 + off);
        }
    }
    __syncthreads();

    // ---- prologue: tile 0 into stage 0 ----
    load_arr64(sb + 0,     KhG + kb, tid);
    load_arr64(sb + 8192,  KlG + kb, tid);
    load_arr64(sb + 16384, VhG + kb, tid);
    load_arr64(sb + 24576, VlG + kb, tid);
    CP_COMMIT();

    float Oa[8][4];
#pragma unroll
    for (int i = 0; i < 8; i++)
#pragma unroll
        for (int j = 0; j < 4; j++) Oa[i][j] = 0.f;
    float Lg = 0.f, Lg8 = 0.f;

    const int rowk = (lane & 7);
    const uint32_t cbk = ((uint32_t)(lane >> 3)) * 16;
    const int rv = (lane & 7) + ((lane >> 3) & 1) * 8;
    const uint32_t cbv = ((uint32_t)((lane >> 4) & 1)) * 16;

    for (int t = 0; t < NSTEP; t++) {
        if (t + 1 < NSTEP) {
            uint32_t db = sb + ((t + 1) & 1) * STG_BYTES;
            size_t gb = kb + (size_t)(t + 1) * TMT * CO;
            load_arr64(db + 0,     KhG + gb, tid);
            load_arr64(db + 8192,  KlG + gb, tid);
            load_arr64(db + 16384, VhG + gb, tid);
            load_arr64(db + 24576, VlG + gb, tid);
            CP_COMMIT();
            CP_WAIT(1);
        } else {
            CP_WAIT(0);
        }
        __syncthreads();

        const uint32_t kh_b = sb + (t & 1) * STG_BYTES;
        const uint32_t kl_b = kh_b + 8192;
        const uint32_t vh_b = kh_b + 16384;
        const uint32_t vl_b = kh_b + 24576;

#pragma unroll
        for (int mbp = 0; mbp < 4; mbp++) {
            uint32_t PH2[2][2], PL2[2][2];
#pragma unroll
            for (int half = 0; half < 2; half++) {
                int mb = mbp * 2 + half;
                float c0 = 0.f, c1 = 0.f, c2 = 0.f, c3 = 0.f;
#pragma unroll
                for (int kc = 0; kc < 2; kc++) {
                    uint32_t off = SWZ128((uint32_t)((mb * 8 + rowk) * 128 + kc * 64) + cbk);
                    uint32_t k0, k1, k2, k3;
                    LDSM_X4(k0, k1, k2, k3, kh_b + off);
                    MMA16816(c0,c1,c2,c3, QH[2*kc][0],QH[2*kc][1],QH[2*kc][2],QH[2*kc][3], k0,k1);
                    MMA16816(c0,c1,c2,c3, QH[2*kc+1][0],QH[2*kc+1][1],QH[2*kc+1][2],QH[2*kc+1][3], k2,k3);
                    MMA16816(c0,c1,c2,c3, QL[2*kc][0],QL[2*kc][1],QL[2*kc][2],QL[2*kc][3], k0,k1);
                    MMA16816(c0,c1,c2,c3, QL[2*kc+1][0],QL[2*kc+1][1],QL[2*kc+1][2],QL[2*kc+1][3], k2,k3);
                    LDSM_X4(k0, k1, k2, k3, kl_b + off);
                    MMA16816(c0,c1,c2,c3, QH[2*kc][0],QH[2*kc][1],QH[2*kc][2],QH[2*kc][3], k0,k1);
                    MMA16816(c0,c1,c2,c3, QH[2*kc+1][0],QH[2*kc+1][1],QH[2*kc+1][2],QH[2*kc+1][3], k2,k3);
                }
                float p0 = ex2f(c0), p1 = ex2f(c1), p2 = ex2f(c2), p3 = ex2f(c3);
                Lg  += p0 + p1;
                Lg8 += p2 + p3;
                uint32_t h01 = pack_bf16(p0, p1);
                uint32_t h23 = pack_bf16(p2, p3);
                float l0 = p0 - __uint_as_float(h01 << 16);
                float l1 = p1 - __uint_as_float(h01 & 0xFFFF0000u);
                float l2 = p2 - __uint_as_float(h23 << 16);
                float l3 = p3 - __uint_as_float(h23 & 0xFFFF0000u);
                PH2[half][0] = h01; PH2[half][1] = h23;
                PL2[half][0] = pack_bf16(l0, l1); PL2[half][1] = pack_bf16(l2, l3);
            }

            // PV for km = mbp (16 m-rows)
            uint32_t a0 = PH2[0][0], a1 = PH2[0][1], a2 = PH2[1][0], a3 = PH2[1][1];
            uint32_t e0 = PL2[0][0], e1 = PL2[0][1], e2 = PL2[1][0], e3 = PL2[1][1];
#pragma unroll
            for (int oc = 0; oc < 4; oc++) {
                uint32_t off = SWZ128((uint32_t)((mbp * 16 + rv) * 128 + oc * 32) + cbv);
                uint32_t v0, v1, v2, v3;
                LDSM_X4T(v0, v1, v2, v3, vh_b + off);
                MMA16816(Oa[2*oc][0],Oa[2*oc][1],Oa[2*oc][2],Oa[2*oc][3], a0,a1,a2,a3, v0,v1);
                MMA16816(Oa[2*oc+1][0],Oa[2*oc+1][1],Oa[2*oc+1][2],Oa[2*oc+1][3], a0,a1,a2,a3, v2,v3);
                MMA16816(Oa[2*oc][0],Oa[2*oc][1],Oa[2*oc][2],Oa[2*oc][3], e0,e1,e2,e3, v0,v1);
                MMA16816(Oa[2*oc+1][0],Oa[2*oc+1][1],Oa[2*oc+1][2],Oa[2*oc+1][3], e0,e1,e2,e3, v2,v3);
                LDSM_X4T(v0, v1, v2, v3, vl_b + off);
                MMA16816(Oa[2*oc][0],Oa[2*oc][1],Oa[2*oc][2],Oa[2*oc][3], a0,a1,a2,a3, v0,v1);
                MMA16816(Oa[2*oc+1][0],Oa[2*oc+1][1],Oa[2*oc+1][2],Oa[2*oc+1][3], a0,a1,a2,a3, v2,v3);
            }
        }
        __syncthreads();
    }

    // ---- reduce L over quad, normalize, stage [64o][64r], store ----
    Lg  += __shfl_xor_sync(0xffffffffu, Lg, 1);
    Lg  += __shfl_xor_sync(0xffffffffu, Lg, 2);
    Lg8 += __shfl_xor_sync(0xffffffffu, Lg8, 1);
    Lg8 += __shfl_xor_sync(0xffffffffu, Lg8, 2);
    float invg = 1.f / Lg, invg8 = 1.f / Lg8;

    float* stg = (float*)smem;    // stage0 area, 16KB
    int g = lane >> 2, u = lane & 3;
    int rA = r0 + g, rB = r0 + 8 + g;
#pragma unroll
    for (int ob = 0; ob < 8; ob++) {
        int o0 = ob * 8 + 2 * u;
        stg[o0 * 64 + rA]       = Oa[ob][0] * invg;
        stg[(o0 + 1) * 64 + rA] = Oa[ob][1] * invg;
        stg[o0 * 64 + rB]       = Oa[ob][2] * invg8;
        stg[(o0 + 1) * 64 + rB] = Oa[ob][3] * invg8;
    }
    __syncthreads();
    for (int idx = tid; idx < CO * TQ; idx += 128) {
        int o = idx >> 6, r = idx & 63;
        Od[((size_t)b * CO + o) * NN + n0 + r] = stg[idx];
    }
}

// ---------------------------------------------------------------------------
// Epilogue: y = wc @ Od + bc -> BN -> ReLU -> out = img + y
// ---------------------------------------------------------------------------
__global__ void __launch_bounds__(256) out_kernel(
    const float* __restrict__ img, const float* __restrict__ wc,
    const float* __restrict__ bc, const float* __restrict__ gamma,
    const float* __restrict__ beta, const float* __restrict__ mean,
    const float* __restrict__ var, float* __restrict__ out)
{
    extern __shared__ float sm[];
    float* Os = sm;
    float* Ws = sm + 64 * 64;

    int b  = blockIdx.y;
    int n0 = blockIdx.x * 64;
    int tid = threadIdx.x;

    const float* Ob = OdG + (size_t)b * CO * NN;
    for (int idx = tid; idx < CO * 64; idx += 256) {
        int o = idx >> 6, j = idx & 63;
        Os[idx] = Ob[(size_t)o * NN + n0 + j];
    }
    for (int idx = tid; idx < CC * CO; idx += 256) Ws[idx] = wc[idx];
    __syncthreads();

    int nx = (tid & 15) * 4;
    int cg = tid >> 4;
    float acc[8][4];
#pragma unroll
    for (int i = 0; i < 8; i++)
#pragma unroll
        for (int j = 0; j < 4; j++) acc[i][j] = 0.f;

#pragma unroll 4
    for (int o = 0; o < CO; o += 2) {
        float4 a0 = *(const float4*)&Os[o * 64 + nx];
        float4 a1 = *(const float4*)&Os[(o + 1) * 64 + nx];
#pragma unroll
        for (int ci = 0; ci < 8; ci++) {
            int c = cg * 8 + ci;
            float2 w2 = *(const float2*)&Ws[c * CO + o];
            acc[ci][0] += w2.x * a0.x + w2.y * a1.x;
            acc[ci][1] += w2.x * a0.y + w2.y * a1.y;
            acc[ci][2] += w2.x * a0.z + w2.y * a1.z;
            acc[ci][3] += w2.x * a0.w + w2.y * a1.w;
        }
    }

#pragma unroll
    for (int ci = 0; ci < 8; ci++) {
        int c = cg * 8 + ci;
        float inv   = gamma[c] * rsqrtf(var[c] + 1e-5f);
        float shift = beta[c] - mean[c] * inv;
        float bias  = bc[c];
        size_t base = (size_t)b * CC * NN + (size_t)c * NN + n0 + nx;
        float4 iv = *(const float4*)&img[base];
        float4 r;
        float y;
        y = (acc[ci][0] + bias) * inv + shift; r.x = iv.x + fmaxf(y, 0.f);
        y = (acc[ci][1] + bias) * inv + shift; r.y = iv.y + fmaxf(y, 0.f);
        y = (acc[ci][2] + bias) * inv + shift; r.z = iv.z + fmaxf(y, 0.f);
        y = (acc[ci][3] + bias) * inv + shift; r.w = iv.w + fmaxf(y, 0.f);
        *(float4*)&out[base] = r;
    }
}

// ---------------------------------------------------------------------------
extern "C" void kernel_launch(void* const* d_in, const int* in_sizes, int n_in,
                              void* d_out, int out_size)
{
    const float* range_x = (const float*)d_in[0];
    const float* img     = (const float*)d_in[1];
    const float* wq      = (const float*)d_in[2];
    const float* bq      = (const float*)d_in[3];
    const float* wk      = (const float*)d_in[4];
    const float* bk      = (const float*)d_in[5];
    const float* wv      = (const float*)d_in[6];
    const float* bv      = (const float*)d_in[7];
    const float* wc      = (const float*)d_in[8];
    const float* bc      = (const float*)d_in[9];
    const float* g       = (const float*)d_in[10];
    const float* be      = (const float*)d_in[11];
    const float* mn      = (const float*)d_in[12];
    const float* vr      = (const float*)d_in[13];
    float* out = (float*)d_out;

    __nv_bfloat16 *qh, *ql, *kh, *kl, *vh, *vl;
    float* od;
    cudaGetSymbolAddress((void**)&qh, QhG);
    cudaGetSymbolAddress((void**)&ql, QlG);
    cudaGetSymbolAddress((void**)&kh, KhG);
    cudaGetSymbolAddress((void**)&kl, KlG);
    cudaGetSymbolAddress((void**)&vh, VhG);
    cudaGetSymbolAddress((void**)&vl, VlG);
    cudaGetSymbolAddress((void**)&od, OdG);

    int smProj = 20480 * sizeof(float);               // 80KB
    int smOut  = (64 * 64 + CC * CO) * sizeof(float); // 48KB

    cudaFuncSetAttribute(proj2_kernel, cudaFuncAttributeMaxDynamicSharedMemorySize, smProj);
    cudaFuncSetAttribute(attn_mma_kernel, cudaFuncAttributeMaxDynamicSharedMemorySize, SMEM_ATTN);
    cudaFuncSetAttribute(out_kernel, cudaFuncAttributeMaxDynamicSharedMemorySize, smOut);

    const float LOG2E = 1.4426950408889634f;
    dim3 gp(NN / 64, BB);   // 64 x 4 = 256 CTAs

    // Q (pre-scaled by log2 e)
    proj2_kernel<<<gp, 256, smProj>>>(range_x, wq, bq, LOG2E, qh, ql,
                                      nullptr, nullptr, 0.f, nullptr, nullptr, 1);
    // K and V share the img tile
    proj2_kernel<<<gp, 256, smProj>>>(img, wk, bk, 1.0f, kh, kl,
                                      wv, bv, 1.0f, vh, vl, 2);

    attn_mma_kernel<<<gp, 128, SMEM_ATTN>>>(od);

    out_kernel<<<gp, 256, smOut>>>(img, wc, bc, g, be, mn, vr, out);
}